// round 5
// baseline (speedup 1.0000x reference)
#include <cuda_runtime.h>
#include <cuda_bf16.h>
#include <stdint.h>

// SimpleMovingAverage: history (64, 336, 862, 3) f32.
// window = last Q=12 steps; 336 iterations of m = mean(window), push m.
//
// R3 showed the single-pass kernel is concurrency-starved (occ 20%, DRAM 46%,
// nothing saturated): only 2586 float2-series exist. Fix: two-pass time split.
//   Pass 1: run the recurrence 252 steps (no output stores), checkpoint the
//           12-deep window state at t = 84, 168, 252 into a __device__ scratch.
//   Pass 2: 4x threads; chunk c in {0..3} starts from input (c=0) or
//           checkpoint c-1, re-sums its window, and writes rows [84c, 84c+84).
// Recurrence per step (per component), critical path = 1 FFMA:
//   m = s / 12;  s = fma(s, 13/12, -w[old]);  w[old] = m
// Ring index kept compile-time static by unrolling in blocks of 12 (84 = 7*12).

#define SMA_Q       12
#define SMA_INLEN   336
#define SMA_OUTLEN  336
#define SMA_ROW     2586          // 862 * 3 floats, contiguous
#define SMA_ROW2    (SMA_ROW / 2) // 1293 float2 per row
#define SMA_BATCH   64
#define SMA_NTHREADS (SMA_BATCH * SMA_ROW2)  // 82752 series (float2 granularity)

#define SMA_CHUNKS  4
#define SMA_CSTEPS  (SMA_OUTLEN / SMA_CHUNKS)  // 84 = 7 * 12

// Checkpoint scratch: window state after 84, 168, 252 steps.
// Layout [ckpt][k][series] for coalesced access. (SMA_CHUNKS-1)*12*82752
// float2 = ~23.8 MB static device memory (allowed; no runtime alloc).
__device__ float2 g_sma_ckpt[(SMA_CHUNKS - 1) * SMA_Q * SMA_NTHREADS];

__global__ __launch_bounds__(128)
void sma_ckpt_kernel(const float* __restrict__ in) {
    int id = blockIdx.x * blockDim.x + threadIdx.x;
    if (id >= SMA_NTHREADS) return;

    int b  = id / SMA_ROW2;
    int j2 = id - b * SMA_ROW2;

    const float2* __restrict__ src =
        reinterpret_cast<const float2*>(
            in + (size_t)b * SMA_INLEN * SMA_ROW
               + (size_t)(SMA_INLEN - SMA_Q) * SMA_ROW) + j2;

    float2 w[SMA_Q];
    float sx = 0.0f, sy = 0.0f;
#pragma unroll
    for (int k = 0; k < SMA_Q; k++) {
        w[k] = src[(size_t)k * SMA_ROW2];
        sx += w[k].x;
        sy += w[k].y;
    }

    const float inv_q = 1.0f / 12.0f;
    const float k1312 = 13.0f / 12.0f;

#pragma unroll 1
    for (int phase = 0; phase < SMA_CHUNKS - 1; phase++) {
#pragma unroll 1
        for (int blk = 0; blk < SMA_CSTEPS / SMA_Q; blk++) {
#pragma unroll
            for (int u = 0; u < SMA_Q; u++) {
                float mx = sx * inv_q;
                float my = sy * inv_q;
                sx = fmaf(sx, k1312, -w[u].x);
                sy = fmaf(sy, k1312, -w[u].y);
                w[u].x = mx;
                w[u].y = my;
            }
        }
        // After a multiple of 12 steps the ring is phase-aligned: w[0] is the
        // oldest element of the logical window at t = 84*(phase+1).
        float2* ck = g_sma_ckpt + (size_t)phase * SMA_Q * SMA_NTHREADS + id;
#pragma unroll
        for (int k = 0; k < SMA_Q; k++) {
            ck[(size_t)k * SMA_NTHREADS] = w[k];
        }
    }
}

__global__ __launch_bounds__(128)
void sma_write_kernel(const float* __restrict__ in, float* __restrict__ out) {
    int id = blockIdx.x * blockDim.x + threadIdx.x;
    if (id >= SMA_NTHREADS) return;
    int chunk = blockIdx.y;

    int b  = id / SMA_ROW2;
    int j2 = id - b * SMA_ROW2;

    // Window source: input tail for chunk 0, checkpoint chunk-1 otherwise.
    const float2* __restrict__ src;
    size_t sstride;
    if (chunk == 0) {
        src = reinterpret_cast<const float2*>(
                  in + (size_t)b * SMA_INLEN * SMA_ROW
                     + (size_t)(SMA_INLEN - SMA_Q) * SMA_ROW) + j2;
        sstride = SMA_ROW2;
    } else {
        src = g_sma_ckpt + (size_t)(chunk - 1) * SMA_Q * SMA_NTHREADS + id;
        sstride = SMA_NTHREADS;
    }

    float2 w[SMA_Q];
    float sx = 0.0f, sy = 0.0f;
#pragma unroll
    for (int k = 0; k < SMA_Q; k++) {
        w[k] = src[(size_t)k * sstride];
        sx += w[k].x;
        sy += w[k].y;
    }

    float2* __restrict__ d =
        reinterpret_cast<float2*>(out + (size_t)b * SMA_OUTLEN * SMA_ROW
                                      + (size_t)chunk * SMA_CSTEPS * SMA_ROW) + j2;

    const float inv_q = 1.0f / 12.0f;
    const float k1312 = 13.0f / 12.0f;

#pragma unroll 1
    for (int blk = 0; blk < SMA_CSTEPS / SMA_Q; blk++) {
#pragma unroll
        for (int u = 0; u < SMA_Q; u++) {
            float mx = sx * inv_q;
            float my = sy * inv_q;
            d[(size_t)u * SMA_ROW2] = make_float2(mx, my);
            sx = fmaf(sx, k1312, -w[u].x);
            sy = fmaf(sy, k1312, -w[u].y);
            w[u].x = mx;
            w[u].y = my;
        }
        d += (size_t)SMA_Q * SMA_ROW2;
    }
}

extern "C" void kernel_launch(void* const* d_in, const int* in_sizes, int n_in,
                              void* d_out, int out_size) {
    (void)in_sizes; (void)n_in; (void)out_size;
    const float* in = (const float*)d_in[0];
    float* out = (float*)d_out;

    const int threads = 128;
    const int blocks = (SMA_NTHREADS + threads - 1) / threads;  // 647

    sma_ckpt_kernel<<<blocks, threads>>>(in);
    dim3 grid2(blocks, SMA_CHUNKS);
    sma_write_kernel<<<grid2, threads>>>(in, out);
}

// round 6
// speedup vs baseline: 1.1559x; 1.1559x over previous
#include <cuda_runtime.h>
#include <cuda_bf16.h>
#include <stdint.h>

// SimpleMovingAverage: history (64, 336, 862, 3) f32.
// window = last Q=12 steps; 336 iterations of m = mean(window), push m.
//
// The recurrence is LINEAR in the initial window: state after T steps is
// w_T = A^T w_0 with A fixed (Q=12). So time-chunk parallelism needs no
// checkpoint pass: chunk c loads the same 12 input values and applies the
// precomputed matrix A^(84c), then runs its 84 output steps.
//   - init kernel (12 threads, ~µs): simulates the recurrence on the 12 basis
//     vectors with the SAME unrolled loop structure, records the window at
//     t = 84, 168, 252 into a tiny __device__ table (transposed for float4
//     loads). Deterministic, graph-capturable, no allocation.
//   - main kernel: grid.y = chunk; thread = one float2 series. Streamed
//     matvec keeps register pressure ~40 (one live window, not two).
// Per-step critical path stays 1 FFMA: m = s/12; s = fma(s, 13/12, -w[u]).
// Output stores use __stcs (never re-read; keep L2 for the input).

#define SMA_Q       12
#define SMA_INLEN   336
#define SMA_OUTLEN  336
#define SMA_ROW     2586          // 862 * 3 floats, contiguous
#define SMA_ROW2    (SMA_ROW / 2) // 1293 float2 per row
#define SMA_BATCH   64
#define SMA_NTHREADS (SMA_BATCH * SMA_ROW2)  // 82752 float2-series

#define SMA_CHUNKS  4
#define SMA_CSTEPS  (SMA_OUTLEN / SMA_CHUNKS)  // 84 = 7 * 12 (ring stays aligned)

// g_matT[c][k][slot]: coefficient of initial-window element k in window slot
// `slot` after 84*(c+1) steps. [k][slot] layout -> 12 contiguous floats per k.
__device__ float g_matT[SMA_CHUNKS - 1][SMA_Q][SMA_Q];

__global__ void sma_init_kernel() {
    int k = threadIdx.x;
    if (k >= SMA_Q) return;

    float w[SMA_Q];
#pragma unroll
    for (int i = 0; i < SMA_Q; i++) w[i] = (i == k) ? 1.0f : 0.0f;
    float s = 1.0f;  // sum of basis window

    const float inv_q = 1.0f / 12.0f;
    const float k1312 = 13.0f / 12.0f;

#pragma unroll 1
    for (int c = 0; c < SMA_CHUNKS - 1; c++) {
#pragma unroll 1
        for (int blk = 0; blk < SMA_CSTEPS / SMA_Q; blk++) {
#pragma unroll
            for (int u = 0; u < SMA_Q; u++) {
                float m = s * inv_q;
                s = fmaf(s, k1312, -w[u]);
                w[u] = m;
            }
        }
#pragma unroll
        for (int slot = 0; slot < SMA_Q; slot++)
            g_matT[c][k][slot] = w[slot];
    }
}

__global__ __launch_bounds__(128)
void sma_main_kernel(const float* __restrict__ in, float* __restrict__ out) {
    int id = blockIdx.x * blockDim.x + threadIdx.x;
    if (id >= SMA_NTHREADS) return;
    int chunk = blockIdx.y;

    int b  = id / SMA_ROW2;
    int j2 = id - b * SMA_ROW2;

    const float2* __restrict__ src =
        reinterpret_cast<const float2*>(
            in + (size_t)b * SMA_INLEN * SMA_ROW
               + (size_t)(SMA_INLEN - SMA_Q) * SMA_ROW) + j2;

    float wx[SMA_Q], wy[SMA_Q];
    float sx = 0.0f, sy = 0.0f;

    if (chunk == 0) {
#pragma unroll
        for (int k = 0; k < SMA_Q; k++) {
            float2 v = src[(size_t)k * SMA_ROW2];
            wx[k] = v.x; wy[k] = v.y;
            sx += v.x;   sy += v.y;
        }
    } else {
        const float* __restrict__ M = &g_matT[chunk - 1][0][0];
#pragma unroll
        for (int slot = 0; slot < SMA_Q; slot++) { wx[slot] = 0.0f; wy[slot] = 0.0f; }
        // Streamed matvec: consume x[k] immediately; only one live window.
#pragma unroll 1
        for (int k = 0; k < SMA_Q; k++) {
            float2 v = src[(size_t)k * SMA_ROW2];
            const float* Mk = M + k * SMA_Q;  // uniform address -> broadcast
#pragma unroll
            for (int slot = 0; slot < SMA_Q; slot++) {
                float c = __ldg(Mk + slot);
                wx[slot] = fmaf(c, v.x, wx[slot]);
                wy[slot] = fmaf(c, v.y, wy[slot]);
            }
        }
#pragma unroll
        for (int slot = 0; slot < SMA_Q; slot++) { sx += wx[slot]; sy += wy[slot]; }
    }

    float2* __restrict__ d =
        reinterpret_cast<float2*>(out + (size_t)b * SMA_OUTLEN * SMA_ROW
                                      + (size_t)chunk * SMA_CSTEPS * SMA_ROW) + j2;

    const float inv_q = 1.0f / 12.0f;
    const float k1312 = 13.0f / 12.0f;

#pragma unroll 1
    for (int blk = 0; blk < SMA_CSTEPS / SMA_Q; blk++) {
#pragma unroll
        for (int u = 0; u < SMA_Q; u++) {
            float mx = sx * inv_q;
            float my = sy * inv_q;
            __stcs(&d[(size_t)u * SMA_ROW2], make_float2(mx, my));
            sx = fmaf(sx, k1312, -wx[u]);
            sy = fmaf(sy, k1312, -wy[u]);
            wx[u] = mx;
            wy[u] = my;
        }
        d += (size_t)SMA_Q * SMA_ROW2;
    }
}

extern "C" void kernel_launch(void* const* d_in, const int* in_sizes, int n_in,
                              void* d_out, int out_size) {
    (void)in_sizes; (void)n_in; (void)out_size;
    const float* in = (const float*)d_in[0];
    float* out = (float*)d_out;

    sma_init_kernel<<<1, 32>>>();

    const int threads = 128;
    const int blocks = (SMA_NTHREADS + threads - 1) / threads;  // 647
    dim3 grid(blocks, SMA_CHUNKS);
    sma_main_kernel<<<grid, threads>>>(in, out);
}